// round 1
// baseline (speedup 1.0000x reference)
#include <cuda_runtime.h>
#include <cuda_fp16.h>
#include <cstdint>

// Problem constants
constexpr int Bb = 4, Ss = 2048, Ee = 1024, Dd = 512;
constexpr int MSUM = Bb * Ss;                // 8192
constexpr float SCALE = 0.04419417382415922f; // 1/sqrt(512)

// ---------------- scratch (static device memory; no allocations) ----------
__device__ __half g_Xh[(size_t)MSUM * Ee];        // 16 MB
__device__ __half g_Wq[(size_t)Ee * Dd];
__device__ __half g_Wk[(size_t)Ee * Dd];
__device__ __half g_Wv[(size_t)Ee * Dd];
__device__ __half g_Q[(size_t)MSUM * Dd];         // 8 MB each
__device__ __half g_K[(size_t)MSUM * Dd];
__device__ __half g_V[(size_t)MSUM * Dd];
__device__ float  g_S[(size_t)Bb * Ss * Ss];      // 64 MB
__device__ __half g_P[(size_t)Bb * Ss * Ss];      // 32 MB

#define DI __device__ __forceinline__

DI uint32_t smem_u32(const void* p) { return (uint32_t)__cvta_generic_to_shared(p); }

DI void cp_async16(uint32_t s, const void* g) {
    asm volatile("cp.async.cg.shared.global [%0], [%1], 16;\n" :: "r"(s), "l"(g));
}
DI void cp_commit() { asm volatile("cp.async.commit_group;\n" ::); }
template <int N> DI void cp_wait() { asm volatile("cp.async.wait_group %0;\n" :: "n"(N)); }

DI void ldsm_x4(uint32_t* r, uint32_t a) {
    asm volatile("ldmatrix.sync.aligned.m8n8.x4.shared.b16 {%0,%1,%2,%3}, [%4];\n"
                 : "=r"(r[0]), "=r"(r[1]), "=r"(r[2]), "=r"(r[3]) : "r"(a));
}
DI void ldsm_x4_t(uint32_t* r, uint32_t a) {
    asm volatile("ldmatrix.sync.aligned.m8n8.x4.trans.shared.b16 {%0,%1,%2,%3}, [%4];\n"
                 : "=r"(r[0]), "=r"(r[1]), "=r"(r[2]), "=r"(r[3]) : "r"(a));
}
DI void mma16816(float* c, const uint32_t* a, uint32_t b0, uint32_t b1) {
    asm volatile(
        "mma.sync.aligned.m16n8k16.row.col.f32.f16.f16.f32 "
        "{%0,%1,%2,%3},{%4,%5,%6,%7},{%8,%9},{%0,%1,%2,%3};\n"
        : "+f"(c[0]), "+f"(c[1]), "+f"(c[2]), "+f"(c[3])
        : "r"(a[0]), "r"(a[1]), "r"(a[2]), "r"(a[3]), "r"(b0), "r"(b1));
}

// ---------------------------------------------------------------------------
// Generic 128x128x32 fp16 GEMM core, 256 threads (8 warps, 4x2; warp tile 32x64).
// BKM=true : B is [N][K] row-major (K contiguous)  -> plain ldmatrix
// BKM=false: B is [K][N] row-major (N contiguous)  -> ldmatrix.trans
// ---------------------------------------------------------------------------
template <bool BKM>
DI void gemm_core(const __half* __restrict__ A, int lda,
                  const __half* __restrict__ B, int ldb,
                  int m0, int n0, int nk, float (&acc)[2][8][4])
{
    __shared__ __align__(16) __half sA[2][128 * 40];
    __shared__ __align__(16) __half sB[2][5120];

    const int tid = threadIdx.x;
    const int lane = tid & 31, warp = tid >> 5;
    const int wm = warp & 3, wn = warp >> 2;

#pragma unroll
    for (int i = 0; i < 2; i++)
#pragma unroll
        for (int j = 0; j < 8; j++)
#pragma unroll
            for (int t = 0; t < 4; t++) acc[i][j][t] = 0.f;

    auto load_stage = [&](int st, int kt) {
        const __half* gA = A + (size_t)m0 * lda + kt * 32;
#pragma unroll
        for (int i = 0; i < 2; i++) {
            int c = tid * 2 + i, r = c >> 2, ch = c & 3;
            cp_async16(smem_u32(&sA[st][r * 40 + ch * 8]), gA + (size_t)r * lda + ch * 8);
        }
        if (BKM) {
            const __half* gB = B + (size_t)n0 * ldb + kt * 32;
#pragma unroll
            for (int i = 0; i < 2; i++) {
                int c = tid * 2 + i, r = c >> 2, ch = c & 3;
                cp_async16(smem_u32(&sB[st][r * 40 + ch * 8]), gB + (size_t)r * ldb + ch * 8);
            }
        } else {
            const __half* gB = B + (size_t)(kt * 32) * ldb + n0;
#pragma unroll
            for (int i = 0; i < 2; i++) {
                int c = tid * 2 + i, r = c >> 4, ch = c & 15;
                cp_async16(smem_u32(&sB[st][r * 136 + ch * 8]), gB + (size_t)r * ldb + ch * 8);
            }
        }
        cp_commit();
    };

    load_stage(0, 0);

    for (int kt = 0; kt < nk; kt++) {
        int cur = kt & 1;
        if (kt + 1 < nk) { load_stage(cur ^ 1, kt + 1); cp_wait<1>(); }
        else            { cp_wait<0>(); }
        __syncthreads();

#pragma unroll
        for (int kk = 0; kk < 2; kk++) {
            uint32_t a[2][4];
#pragma unroll
            for (int mf = 0; mf < 2; mf++) {
                int row = wm * 32 + mf * 16 + (lane & 15);
                int col = kk * 16 + (lane >> 4) * 8;
                ldsm_x4(a[mf], smem_u32(&sA[cur][row * 40 + col]));
            }
            uint32_t bf[4][4];
#pragma unroll
            for (int p = 0; p < 4; p++) {
                if (BKM) {
                    int n = wn * 64 + p * 16 + ((lane >> 4) << 3) + (lane & 7);
                    int k = kk * 16 + ((lane >> 3) & 1) * 8;
                    ldsm_x4(bf[p], smem_u32(&sB[cur][n * 40 + k]));
                } else {
                    int k = kk * 16 + ((lane >> 3) & 1) * 8 + (lane & 7);
                    int n = wn * 64 + p * 16 + (lane >> 4) * 8;
                    ldsm_x4_t(bf[p], smem_u32(&sB[cur][k * 136 + n]));
                }
            }
#pragma unroll
            for (int mf = 0; mf < 2; mf++)
#pragma unroll
                for (int p = 0; p < 4; p++) {
                    mma16816(acc[mf][2 * p],     a[mf], bf[p][0], bf[p][1]);
                    mma16816(acc[mf][2 * p + 1], a[mf], bf[p][2], bf[p][3]);
                }
        }
        __syncthreads();
    }
}

// ---------------------------------------------------------------------------
// Kernel 0: fp32 -> fp16 conversion into device scratch
// ---------------------------------------------------------------------------
__global__ void cvt_kernel(const float* __restrict__ in, int n, int which) {
    __half* out = (which == 0) ? g_Xh : (which == 1) ? g_Wq : (which == 2) ? g_Wk : g_Wv;
    for (int i = blockIdx.x * blockDim.x + threadIdx.x; i < n; i += gridDim.x * blockDim.x)
        out[i] = __float2half(in[i]);
}

// ---------------------------------------------------------------------------
// Kernel 1: QKV projection. grid = (N/128=4, M/128=64, 3)
// ---------------------------------------------------------------------------
__global__ __launch_bounds__(256) void qkv_kernel(const float* __restrict__ bq,
                                                  const float* __restrict__ bk,
                                                  const float* __restrict__ bv)
{
    int z = blockIdx.z;
    const __half* W   = (z == 0) ? g_Wq : (z == 1) ? g_Wk : g_Wv;
    const float* bias = (z == 0) ? bq   : (z == 1) ? bk   : bv;
    __half* out       = (z == 0) ? g_Q  : (z == 1) ? g_K  : g_V;

    int m0 = blockIdx.y * 128, n0 = blockIdx.x * 128;
    float acc[2][8][4];
    gemm_core<false>(g_Xh, Ee, W, Dd, m0, n0, Ee / 32, acc);

    const int lane = threadIdx.x & 31, warp = threadIdx.x >> 5;
    const int wm = warp & 3, wn = warp >> 2;
    const int grp = lane >> 2, qd = (lane & 3) * 2;
#pragma unroll
    for (int mf = 0; mf < 2; mf++)
#pragma unroll
        for (int nf = 0; nf < 8; nf++) {
            int m = m0 + wm * 32 + mf * 16 + grp;
            int n = n0 + wn * 64 + nf * 8 + qd;
            float b0 = bias[n], b1 = bias[n + 1];
            *(__half2*)&out[(size_t)m * Dd + n] =
                __floats2half2_rn(acc[mf][nf][0] + b0, acc[mf][nf][1] + b1);
            *(__half2*)&out[(size_t)(m + 8) * Dd + n] =
                __floats2half2_rn(acc[mf][nf][2] + b0, acc[mf][nf][3] + b1);
        }
}

// ---------------------------------------------------------------------------
// Kernel 2: scores = scale * Q @ K^T (lower-triangle tiles only)
// grid = (16, 16, 4); tile (bx,by) with bx > by skipped.
// ---------------------------------------------------------------------------
__global__ __launch_bounds__(256) void scores_kernel()
{
    if (blockIdx.x > blockIdx.y) return;  // strictly above diagonal: never read
    int b = blockIdx.z;
    const __half* A = g_Q + (size_t)b * Ss * Dd;
    const __half* B = g_K + (size_t)b * Ss * Dd;
    float* out = g_S + (size_t)b * Ss * Ss;

    int m0 = blockIdx.y * 128, n0 = blockIdx.x * 128;
    float acc[2][8][4];
    gemm_core<true>(A, Dd, B, Dd, m0, n0, Dd / 32, acc);

    const int lane = threadIdx.x & 31, warp = threadIdx.x >> 5;
    const int wm = warp & 3, wn = warp >> 2;
    const int grp = lane >> 2, qd = (lane & 3) * 2;
#pragma unroll
    for (int mf = 0; mf < 2; mf++)
#pragma unroll
        for (int nf = 0; nf < 8; nf++) {
            int m = m0 + wm * 32 + mf * 16 + grp;
            int n = n0 + wn * 64 + nf * 8 + qd;
            float2 v0 = make_float2(acc[mf][nf][0] * SCALE, acc[mf][nf][1] * SCALE);
            float2 v1 = make_float2(acc[mf][nf][2] * SCALE, acc[mf][nf][3] * SCALE);
            *(float2*)&out[(size_t)m * Ss + n] = v0;
            *(float2*)&out[(size_t)(m + 8) * Ss + n] = v1;
        }
}

// ---------------------------------------------------------------------------
// Kernel 3: causal softmax per row; writes P (fp16) with zeros above diagonal.
// grid = 8192 CTAs x 256 threads.
// ---------------------------------------------------------------------------
__global__ __launch_bounds__(256) void softmax_kernel()
{
    const int row = blockIdx.x;          // b*2048 + q
    const int q = row & (Ss - 1);
    const int len = q + 1;
    const float* srow = g_S + (size_t)row * Ss;
    __half* prow = g_P + (size_t)row * Ss;

    __shared__ float buf[Ss];
    __shared__ float red[8];
    const int tid = threadIdx.x;

    float lmax = -1e30f;
    for (int c = tid; c < len; c += 256) {
        float v = srow[c];
        buf[c] = v;
        lmax = fmaxf(lmax, v);
    }
#pragma unroll
    for (int o = 16; o > 0; o >>= 1) lmax = fmaxf(lmax, __shfl_xor_sync(0xffffffffu, lmax, o));
    if ((tid & 31) == 0) red[tid >> 5] = lmax;
    __syncthreads();
    if (tid < 32) {
        float v = (tid < 8) ? red[tid] : -1e30f;
#pragma unroll
        for (int o = 4; o > 0; o >>= 1) v = fmaxf(v, __shfl_xor_sync(0xffffffffu, v, o));
        if (tid == 0) red[0] = v;
    }
    __syncthreads();
    const float rmax = red[0];
    __syncthreads();

    float lsum = 0.f;
    for (int c = tid; c < len; c += 256) {
        float e = __expf(buf[c] - rmax);
        buf[c] = e;
        lsum += e;
    }
#pragma unroll
    for (int o = 16; o > 0; o >>= 1) lsum += __shfl_xor_sync(0xffffffffu, lsum, o);
    if ((tid & 31) == 0) red[tid >> 5] = lsum;
    __syncthreads();
    if (tid < 32) {
        float v = (tid < 8) ? red[tid] : 0.f;
#pragma unroll
        for (int o = 4; o > 0; o >>= 1) v += __shfl_xor_sync(0xffffffffu, v, o);
        if (tid == 0) red[0] = v;
    }
    __syncthreads();
    const float inv = 1.0f / red[0];

    for (int c = tid; c < Ss; c += 256)
        prow[c] = __float2half((c < len) ? buf[c] * inv : 0.f);
}

// ---------------------------------------------------------------------------
// Kernel 4: out = P @ V, K-loop truncated at the causal diagonal.
// grid = (4, 16, 4)
// ---------------------------------------------------------------------------
__global__ __launch_bounds__(256) void out_kernel(float* __restrict__ Out)
{
    int b = blockIdx.z;
    const __half* A = g_P + (size_t)b * Ss * Ss;
    const __half* Bv = g_V + (size_t)b * Ss * Dd;
    float* out = Out + (size_t)b * Ss * Dd;

    int m0 = blockIdx.y * 128, n0 = blockIdx.x * 128;
    int nk = (blockIdx.y + 1) * 4;           // k only up to diagonal tile
    if (nk > Ss / 32) nk = Ss / 32;

    float acc[2][8][4];
    gemm_core<false>(A, Ss, Bv, Dd, m0, n0, nk, acc);

    const int lane = threadIdx.x & 31, warp = threadIdx.x >> 5;
    const int wm = warp & 3, wn = warp >> 2;
    const int grp = lane >> 2, qd = (lane & 3) * 2;
#pragma unroll
    for (int mf = 0; mf < 2; mf++)
#pragma unroll
        for (int nf = 0; nf < 8; nf++) {
            int m = m0 + wm * 32 + mf * 16 + grp;
            int n = n0 + wn * 64 + nf * 8 + qd;
            *(float2*)&out[(size_t)m * Dd + n] = make_float2(acc[mf][nf][0], acc[mf][nf][1]);
            *(float2*)&out[(size_t)(m + 8) * Dd + n] = make_float2(acc[mf][nf][2], acc[mf][nf][3]);
        }
}

// ---------------------------------------------------------------------------
extern "C" void kernel_launch(void* const* d_in, const int* in_sizes, int n_in,
                              void* d_out, int out_size)
{
    const float* x  = (const float*)d_in[0];
    const float* wq = (const float*)d_in[1];
    const float* bq = (const float*)d_in[2];
    const float* wk = (const float*)d_in[3];
    const float* bk = (const float*)d_in[4];
    const float* wv = (const float*)d_in[5];
    const float* bv = (const float*)d_in[6];

    cvt_kernel<<<4096, 256>>>(x,  MSUM * Ee, 0);
    cvt_kernel<<<1024, 256>>>(wq, Ee * Dd,   1);
    cvt_kernel<<<1024, 256>>>(wk, Ee * Dd,   2);
    cvt_kernel<<<1024, 256>>>(wv, Ee * Dd,   3);

    qkv_kernel<<<dim3(4, 64, 3), 256>>>(bq, bk, bv);
    scores_kernel<<<dim3(16, 16, 4), 256>>>();
    softmax_kernel<<<MSUM, 256>>>();
    out_kernel<<<dim3(4, 16, 4), 256>>>((float*)d_out);
}

// round 3
// speedup vs baseline: 1.0780x; 1.0780x over previous
#include <cuda_runtime.h>
#include <cuda_fp16.h>
#include <cstdint>

// Problem constants
constexpr int Bb = 4, Ss = 2048, Ee = 1024, Dd = 512;
constexpr int MSUM = Bb * Ss;                  // 8192
constexpr float SCALE = 0.04419417382415922f; // 1/sqrt(512)

// ---------------- scratch (static device memory; no allocations) ----------
__device__ __align__(256) __half g_Xh[(size_t)MSUM * Ee];   // 16 MB
__device__ __align__(256) __half g_Wq[(size_t)Ee * Dd];     // TRANSPOSED [D][E]
__device__ __align__(256) __half g_Wk[(size_t)Ee * Dd];
__device__ __align__(256) __half g_Wv[(size_t)Ee * Dd];
__device__ __align__(256) __half g_Q [(size_t)MSUM * Dd];
__device__ __align__(256) __half g_K [(size_t)MSUM * Dd];
__device__ __align__(256) __half g_V [(size_t)MSUM * Dd];
__device__ __align__(256) __half g_Vt[(size_t)MSUM * Dd];   // [b][d][s]
__device__ __align__(256) float  g_S [(size_t)Bb * Ss * Ss]; // 64 MB
__device__ __align__(256) __half g_P [(size_t)Bb * Ss * Ss]; // 32 MB

#define DI __device__ __forceinline__

DI uint32_t smem_u32(const void* p) { return (uint32_t)__cvta_generic_to_shared(p); }

DI void cp_async16(uint32_t s, const void* g) {
    asm volatile("cp.async.cg.shared.global [%0], [%1], 16;\n" :: "r"(s), "l"(g));
}
DI void cp_commit() { asm volatile("cp.async.commit_group;\n" ::); }
template <int N> DI void cp_wait() { asm volatile("cp.async.wait_group %0;\n" :: "n"(N)); }

DI void ldsm_x4(uint32_t* r, uint32_t a) {
    asm volatile("ldmatrix.sync.aligned.m8n8.x4.shared.b16 {%0,%1,%2,%3}, [%4];\n"
                 : "=r"(r[0]), "=r"(r[1]), "=r"(r[2]), "=r"(r[3]) : "r"(a));
}
DI void mma16816(float* c, const uint32_t* a, uint32_t b0, uint32_t b1) {
    asm volatile(
        "mma.sync.aligned.m16n8k16.row.col.f32.f16.f16.f32 "
        "{%0,%1,%2,%3},{%4,%5,%6,%7},{%8,%9},{%0,%1,%2,%3};\n"
        : "+f"(c[0]), "+f"(c[1]), "+f"(c[2]), "+f"(c[3])
        : "r"(a[0]), "r"(a[1]), "r"(a[2]), "r"(a[3]), "r"(b0), "r"(b1));
}

// ---------------------------------------------------------------------------
// HMMA GEMM core: CTA tile 128x128, 4 warps (2x2), warp tile 64x64.
// K in steps of 32, 4-stage cp.async pipeline.
// A: [M][K] K-major (lda). B: [N][K] K-major (ldb).  C = A * B^T
// MODE 0: fp16 out + bias.  MODE 1: fp32 out * SCALE.  MODE 2: fp32 out.
// ---------------------------------------------------------------------------
constexpr int STAGES = 4;
constexpr int TILE_H = 128 * 40 * 2;        // one padded tile: 10240 B
constexpr int STAGE_B = 2 * TILE_H;         // A + B per stage: 20480 B
constexpr int DSMEM_SIZE = STAGES * STAGE_B; // 81920 B

template <int MODE>
DI void mma_core(const __half* __restrict__ A, int lda,
                 const __half* __restrict__ B, int ldb,
                 int m0, int n0, int nk,
                 float* __restrict__ outF, __half* __restrict__ outH, int ldo,
                 const float* __restrict__ bias)
{
    extern __shared__ __align__(16) char smem[];
    const uint32_t base = smem_u32(smem);

    const int tid = threadIdx.x;
    const int lane = tid & 31, warp = tid >> 5;
    const int wm = warp & 1, wn = warp >> 1;

    float acc[4][8][4];
#pragma unroll
    for (int i = 0; i < 4; i++)
#pragma unroll
        for (int j = 0; j < 8; j++)
#pragma unroll
            for (int t = 0; t < 4; t++) acc[i][j][t] = 0.f;

    auto load_stage = [&](int st, int kt) {
        const __half* gA = A + (size_t)m0 * lda + kt * 32;
        const __half* gB = B + (size_t)n0 * ldb + kt * 32;
        const uint32_t aB = base + st * STAGE_B;
        const uint32_t bB = aB + TILE_H;
#pragma unroll
        for (int j = 0; j < 4; j++) {
            int idx = tid + j * 128, r = idx >> 2, ch = idx & 3;
            cp_async16(aB + (r * 40 + ch * 8) * 2, gA + (size_t)r * lda + ch * 8);
        }
#pragma unroll
        for (int j = 0; j < 4; j++) {
            int idx = tid + j * 128, r = idx >> 2, ch = idx & 3;
            cp_async16(bB + (r * 40 + ch * 8) * 2, gB + (size_t)r * ldb + ch * 8);
        }
        cp_commit();
    };

    // prefetch STAGES-1 stages (pad with empty groups to keep wait arithmetic uniform)
#pragma unroll
    for (int s = 0; s < STAGES - 1; s++) {
        if (s < nk) load_stage(s, s); else cp_commit();
    }

    for (int kt = 0; kt < nk; kt++) {
        const int cur = kt % STAGES;
        cp_wait<STAGES - 2>();
        __syncthreads();
        // issue next load (overwrites stage used in PREVIOUS iteration — safe post-sync)
        if (kt + STAGES - 1 < nk) load_stage((kt + STAGES - 1) % STAGES, kt + STAGES - 1);
        else cp_commit();

        const uint32_t aT = base + cur * STAGE_B;
        const uint32_t bT = aT + TILE_H;
#pragma unroll
        for (int kk = 0; kk < 2; kk++) {
            uint32_t a[4][4];
#pragma unroll
            for (int mf = 0; mf < 4; mf++) {
                int row = wm * 64 + mf * 16 + (lane & 15);
                int col = kk * 16 + (lane >> 4) * 8;
                ldsm_x4(a[mf], aT + (row * 40 + col) * 2);
            }
            uint32_t bf[4][4];
#pragma unroll
            for (int p = 0; p < 4; p++) {
                int n = wn * 64 + p * 16 + ((lane >> 4) << 3) + (lane & 7);
                int k = kk * 16 + ((lane >> 3) & 1) * 8;
                ldsm_x4(bf[p], bT + (n * 40 + k) * 2);
            }
#pragma unroll
            for (int mf = 0; mf < 4; mf++)
#pragma unroll
                for (int p = 0; p < 4; p++) {
                    mma16816(acc[mf][2 * p],     a[mf], bf[p][0], bf[p][1]);
                    mma16816(acc[mf][2 * p + 1], a[mf], bf[p][2], bf[p][3]);
                }
        }
    }

    // Epilogue: direct stores from accumulators
    const int grp = lane >> 2, qd = (lane & 3) * 2;
#pragma unroll
    for (int nf = 0; nf < 8; nf++) {
        const int n = n0 + wn * 64 + nf * 8 + qd;
        float b0 = 0.f, b1 = 0.f;
        if (MODE == 0) { b0 = bias[n]; b1 = bias[n + 1]; }
#pragma unroll
        for (int mf = 0; mf < 4; mf++) {
            const int m = m0 + wm * 64 + mf * 16 + grp;
            if (MODE == 0) {
                *(__half2*)&outH[(size_t)m * ldo + n] =
                    __floats2half2_rn(acc[mf][nf][0] + b0, acc[mf][nf][1] + b1);
                *(__half2*)&outH[(size_t)(m + 8) * ldo + n] =
                    __floats2half2_rn(acc[mf][nf][2] + b0, acc[mf][nf][3] + b1);
            } else {
                const float sc = (MODE == 1) ? SCALE : 1.0f;
                *(float2*)&outF[(size_t)m * ldo + n] =
                    make_float2(acc[mf][nf][0] * sc, acc[mf][nf][1] * sc);
                *(float2*)&outF[(size_t)(m + 8) * ldo + n] =
                    make_float2(acc[mf][nf][2] * sc, acc[mf][nf][3] * sc);
            }
        }
    }
}

// ---------------------------------------------------------------------------
// x fp32 -> fp16 (vectorized)
// ---------------------------------------------------------------------------
__global__ void cvtx_kernel(const float4* __restrict__ in) {
    const int n4 = MSUM * Ee / 4;
    for (int i = blockIdx.x * blockDim.x + threadIdx.x; i < n4; i += gridDim.x * blockDim.x) {
        float4 v = in[i];
        __half2 a = __floats2half2_rn(v.x, v.y), b = __floats2half2_rn(v.z, v.w);
        uint2 u;
        *(__half2*)&u.x = a; *(__half2*)&u.y = b;
        ((uint2*)g_Xh)[i] = u;
    }
}

// Weights: [E][D] fp32 -> [D][E] fp16 transpose. grid(D/32, E/32, 3), block(32,8)
__global__ void wT_kernel(const float* __restrict__ wq_, const float* __restrict__ wk_,
                          const float* __restrict__ wv_) {
    __shared__ float t[32][33];
    const int z = blockIdx.z;
    const float* in = (z == 0) ? wq_ : (z == 1) ? wk_ : wv_;
    __half* out = (z == 0) ? g_Wq : (z == 1) ? g_Wk : g_Wv;
    const int d0 = blockIdx.x * 32, e0 = blockIdx.y * 32;
    const int tx = threadIdx.x, ty = threadIdx.y;
#pragma unroll
    for (int j = 0; j < 4; j++) t[ty + j * 8][tx] = in[(size_t)(e0 + ty + j * 8) * Dd + d0 + tx];
    __syncthreads();
#pragma unroll
    for (int j = 0; j < 4; j++)
        out[(size_t)(d0 + ty + j * 8) * Ee + e0 + tx] = __float2half(t[tx][ty + j * 8]);
}

// V: [b][s][d] -> [b][d][s]. grid(D/32, S/32, 4), block(32,8)
__global__ void vT_kernel() {
    __shared__ __half t[32][34];
    const int b = blockIdx.z;
    const int d0 = blockIdx.x * 32, s0 = blockIdx.y * 32;
    const __half* in = g_V + (size_t)b * Ss * Dd;
    __half* out = g_Vt + (size_t)b * Dd * Ss;
    const int tx = threadIdx.x, ty = threadIdx.y;
#pragma unroll
    for (int j = 0; j < 4; j++) t[ty + j * 8][tx] = in[(size_t)(s0 + ty + j * 8) * Dd + d0 + tx];
    __syncthreads();
#pragma unroll
    for (int j = 0; j < 4; j++)
        out[(size_t)(d0 + ty + j * 8) * Ss + s0 + tx] = t[tx][ty + j * 8];
}

// ---------------------------------------------------------------------------
// QKV projection: grid (4, 64, 3)
// ---------------------------------------------------------------------------
__global__ __launch_bounds__(128) void qkv_kernel(const float* __restrict__ bq,
                                                  const float* __restrict__ bk,
                                                  const float* __restrict__ bv) {
    const int z = blockIdx.z;
    const __half* W = (z == 0) ? g_Wq : (z == 1) ? g_Wk : g_Wv;  // [D][E]
    const float* bias = (z == 0) ? bq : (z == 1) ? bk : bv;
    __half* out = (z == 0) ? g_Q : (z == 1) ? g_K : g_V;
    mma_core<0>(g_Xh, Ee, W, Ee, blockIdx.y * 128, blockIdx.x * 128, Ee / 32,
                nullptr, out, Dd, bias);
}

// Scores: grid (16, 16, 4), lower-triangle tiles only
__global__ __launch_bounds__(128) void scores_kernel() {
    if (blockIdx.x > blockIdx.y) return;
    const int b = blockIdx.z;
    mma_core<1>(g_Q + (size_t)b * Ss * Dd, Dd, g_K + (size_t)b * Ss * Dd, Dd,
                blockIdx.y * 128, blockIdx.x * 128, Dd / 32,
                g_S + (size_t)b * Ss * Ss, nullptr, Ss, nullptr);
}

// Output: grid (4, 16, 4); heavy (large-K) blocks first; K truncated at diagonal
__global__ __launch_bounds__(128) void out_kernel(float* __restrict__ Out) {
    const int b = blockIdx.z;
    const int by = 15 - blockIdx.y;          // schedule heavy tiles first
    const int nk = (by + 1) * 4;             // K up to (by+1)*128 halves, steps of 32
    mma_core<2>(g_P + (size_t)b * Ss * Ss, Ss, g_Vt + (size_t)b * Dd * Ss, Ss,
                by * 128, blockIdx.x * 128, nk,
                Out + (size_t)b * Ss * Dd, nullptr, Dd, nullptr);
}

// ---------------------------------------------------------------------------
// Causal softmax
// ---------------------------------------------------------------------------
__global__ __launch_bounds__(256) void softmax_kernel() {
    const int row = blockIdx.x;
    const int q = row & (Ss - 1);
    const int len = q + 1;
    const float* srow = g_S + (size_t)row * Ss;
    __half* prow = g_P + (size_t)row * Ss;

    __shared__ float buf[Ss];
    __shared__ float red[8];
    const int tid = threadIdx.x;

    float lmax = -1e30f;
    for (int c = tid; c < len; c += 256) {
        float v = srow[c];
        buf[c] = v;
        lmax = fmaxf(lmax, v);
    }
#pragma unroll
    for (int o = 16; o > 0; o >>= 1) lmax = fmaxf(lmax, __shfl_xor_sync(0xffffffffu, lmax, o));
    if ((tid & 31) == 0) red[tid >> 5] = lmax;
    __syncthreads();
    if (tid < 32) {
        float v = (tid < 8) ? red[tid] : -1e30f;
#pragma unroll
        for (int o = 4; o > 0; o >>= 1) v = fmaxf(v, __shfl_xor_sync(0xffffffffu, v, o));
        if (tid == 0) red[0] = v;
    }
    __syncthreads();
    const float rmax = red[0];
    __syncthreads();

    float lsum = 0.f;
    for (int c = tid; c < len; c += 256) {
        float e = __expf(buf[c] - rmax);
        buf[c] = e;
        lsum += e;
    }
#pragma unroll
    for (int o = 16; o > 0; o >>= 1) lsum += __shfl_xor_sync(0xffffffffu, lsum, o);
    if ((tid & 31) == 0) red[tid >> 5] = lsum;
    __syncthreads();
    if (tid < 32) {
        float v = (tid < 8) ? red[tid] : 0.f;
#pragma unroll
        for (int o = 4; o > 0; o >>= 1) v += __shfl_xor_sync(0xffffffffu, v, o);
        if (tid == 0) red[0] = v;
    }
    __syncthreads();
    const float inv = 1.0f / red[0];

    for (int c = tid; c < Ss; c += 256)
        prow[c] = __float2half((c < len) ? buf[c] * inv : 0.f);
}

// ---------------------------------------------------------------------------
extern "C" void kernel_launch(void* const* d_in, const int* in_sizes, int n_in,
                              void* d_out, int out_size)
{
    const float* x  = (const float*)d_in[0];
    const float* wq = (const float*)d_in[1];
    const float* bq = (const float*)d_in[2];
    const float* wk = (const float*)d_in[3];
    const float* bk = (const float*)d_in[4];
    const float* wv = (const float*)d_in[5];
    const float* bv = (const float*)d_in[6];

    cudaFuncSetAttribute(qkv_kernel,    cudaFuncAttributeMaxDynamicSharedMemorySize, DSMEM_SIZE);
    cudaFuncSetAttribute(scores_kernel, cudaFuncAttributeMaxDynamicSharedMemorySize, DSMEM_SIZE);
    cudaFuncSetAttribute(out_kernel,    cudaFuncAttributeMaxDynamicSharedMemorySize, DSMEM_SIZE);

    cvtx_kernel<<<2048, 256>>>((const float4*)x);
    wT_kernel<<<dim3(16, 32, 3), dim3(32, 8)>>>(wq, wk, wv);
    qkv_kernel<<<dim3(4, 64, 3), 128, DSMEM_SIZE>>>(bq, bk, bv);
    vT_kernel<<<dim3(16, 64, 4), dim3(32, 8)>>>();
    scores_kernel<<<dim3(16, 16, 4), 128, DSMEM_SIZE>>>();
    softmax_kernel<<<MSUM, 256>>>();
    out_kernel<<<dim3(4, 16, 4), 128, DSMEM_SIZE>>>((float*)d_out);
}